// round 2
// baseline (speedup 1.0000x reference)
#include <cuda_runtime.h>
#include <cuda_bf16.h>
#include <math.h>

#define S_LEN 2048
#define DIM 2048
#define NH 32
#define NKV 8
#define HD 64
#define KVDIM (NKV * HD)   // 512

// ---------------------------------------------------------------------------
// Scratch (__device__ globals; no runtime allocation allowed)
// ---------------------------------------------------------------------------
__device__ float g_q[S_LEN * DIM];                       // 16 MB
__device__ float g_k[S_LEN * KVDIM];                     // 4 MB
__device__ float g_v[S_LEN * KVDIM];                     // 4 MB
__device__ float g_ao[S_LEN * DIM];                      // 16 MB
__device__ float g_sc[(size_t)NH * S_LEN * S_LEN];       // 537 MB scores/probs
__device__ float g_ct[S_LEN * 32];
__device__ float g_st[S_LEN * 32];

// ---------------------------------------------------------------------------
// GEMM: C[M,N] = A[M,K] @ B[N,K]^T, row-major. 64x64 tile, BK=16, 256 thr.
// ---------------------------------------------------------------------------
__global__ __launch_bounds__(256)
void gemm_nt(const float* __restrict__ A, const float* __restrict__ B,
             float* __restrict__ C, int M, int N, int K) {
    __shared__ float As[16][64];
    __shared__ float Bs[16][64];
    const int tid = threadIdx.x;
    const int ty = tid >> 4;     // 0..15
    const int tx = tid & 15;     // 0..15
    const int by = blockIdx.y;
    const int bx = blockIdx.x;

    float acc[4][4] = {};

    for (int k0 = 0; k0 < K; k0 += 16) {
        for (int e = tid; e < 64 * 16; e += 256) {
            int r = e >> 4;          // 0..63 (tile row)
            int kk = e & 15;         // 0..15
            As[kk][r] = A[(size_t)(by * 64 + r) * K + k0 + kk];
            Bs[kk][r] = B[(size_t)(bx * 64 + r) * K + k0 + kk];
        }
        __syncthreads();
#pragma unroll
        for (int kk = 0; kk < 16; kk++) {
            float a[4], b[4];
#pragma unroll
            for (int i = 0; i < 4; i++) a[i] = As[kk][ty * 4 + i];
#pragma unroll
            for (int j = 0; j < 4; j++) b[j] = Bs[kk][tx * 4 + j];
#pragma unroll
            for (int i = 0; i < 4; i++)
#pragma unroll
                for (int j = 0; j < 4; j++)
                    acc[i][j] = fmaf(a[i], b[j], acc[i][j]);
        }
        __syncthreads();
    }
#pragma unroll
    for (int i = 0; i < 4; i++)
#pragma unroll
        for (int j = 0; j < 4; j++)
            C[(size_t)(by * 64 + ty * 4 + i) * N + bx * 64 + tx * 4 + j] = acc[i][j];
}

// ---------------------------------------------------------------------------
// RoPE cos/sin table. Mimics reference fp32 angle, high-precision trig.
// ---------------------------------------------------------------------------
__global__ void rope_table_kernel() {
    int s = blockIdx.x;
    int i = threadIdx.x;   // 0..31
    float e = (float)i / 32.0f;
    float fr = 1.0f / powf(10000.0f, e);        // inv_freq, fp32 like reference
    float angf = (float)s * fr;                 // fp32 angle like reference
    double ang = (double)angf;
    g_ct[s * 32 + i] = (float)cos(ang);
    g_st[s * 32 + i] = (float)sin(ang);
}

// ---------------------------------------------------------------------------
// RoPE applied in-place to g_q [S, 32*64] and g_k [S, 8*64]
// ---------------------------------------------------------------------------
__global__ __launch_bounds__(256)
void rope_apply_kernel() {
    const int s = blockIdx.x;
    for (int item = threadIdx.x; item < (NH + NKV) * 32; item += 256) {
        float* base;
        int i;
        if (item < NH * 32) {
            int h = item >> 5; i = item & 31;
            base = g_q + (size_t)s * DIM + h * HD;
        } else {
            int it = item - NH * 32;
            int h = it >> 5; i = it & 31;
            base = g_k + (size_t)s * KVDIM + h * HD;
        }
        float c  = g_ct[s * 32 + i];
        float sn = g_st[s * 32 + i];
        float x1 = base[i], x2 = base[i + 32];
        base[i]      = x1 * c - x2 * sn;
        base[i + 32] = x2 * c + x1 * sn;
    }
}

// ---------------------------------------------------------------------------
// QK: g_sc[h][q][k] = 0.125 * q[q, h*64:..] . k[k, (h>>2)*64:..]; -inf if k>q
// grid (64 ktiles, 64 qtiles, 32 heads), block (32, 32)
// ---------------------------------------------------------------------------
__global__ __launch_bounds__(1024)
void qk_kernel() {
    const int kt = blockIdx.x, qt = blockIdx.y, h = blockIdx.z;
    const int kvh = h >> 2;
    const int tx = threadIdx.x;   // key within tile
    const int ty = threadIdx.y;   // query within tile
    const int qpos = qt * 32 + ty;
    const int kpos = kt * 32 + tx;
    const size_t idx = ((size_t)h * S_LEN + qpos) * S_LEN + kpos;

    if (kt > qt) { g_sc[idx] = -INFINITY; return; }

    __shared__ float Qs[32][65];
    __shared__ float Ks[32][65];
    const int tid = ty * 32 + tx;
    for (int e = tid; e < 32 * 64; e += 1024) {
        int r = e >> 6, d = e & 63;
        Qs[r][d] = g_q[(size_t)(qt * 32 + r) * DIM + h * HD + d];
        Ks[r][d] = g_k[(size_t)(kt * 32 + r) * KVDIM + kvh * HD + d];
    }
    __syncthreads();

    float acc = 0.f;
#pragma unroll
    for (int d = 0; d < 64; d++) acc = fmaf(Qs[ty][d], Ks[tx][d], acc);

    g_sc[idx] = (kpos <= qpos) ? acc * 0.125f : -INFINITY;
}

// ---------------------------------------------------------------------------
// Exact row softmax over g_sc[h][q][:]. grid (2048 rows, 32 heads), 256 thr.
// ---------------------------------------------------------------------------
__global__ __launch_bounds__(256)
void softmax_kernel() {
    const int q = blockIdx.x, h = blockIdx.y;
    float* row = g_sc + ((size_t)h * S_LEN + q) * S_LEN;
    __shared__ float red[256];
    const int tid = threadIdx.x;

    float m = -INFINITY;
    for (int j = tid; j < S_LEN; j += 256) m = fmaxf(m, row[j]);
    red[tid] = m;
    __syncthreads();
    for (int s = 128; s > 0; s >>= 1) {
        if (tid < s) red[tid] = fmaxf(red[tid], red[tid + s]);
        __syncthreads();
    }
    m = red[0];
    __syncthreads();

    float e = 0.f;
    for (int j = tid; j < S_LEN; j += 256) {
        float p = expf(row[j] - m);   // exp(-inf) = 0 handles the mask
        row[j] = p;
        e += p;
    }
    red[tid] = e;
    __syncthreads();
    for (int s = 128; s > 0; s >>= 1) {
        if (tid < s) red[tid] += red[tid + s];
        __syncthreads();
    }
    const float inv = 1.0f / red[0];
    for (int j = tid; j < S_LEN; j += 256) row[j] *= inv;
}

// ---------------------------------------------------------------------------
// PV: g_ao[q, h*64+d] = sum_k P[h][q][k] * v[k, (h>>2)*64+d]
// grid (64 qtiles, 32 heads), 256 threads. ty=tid/64 (0..3), tx=tid%64 (dim)
// ---------------------------------------------------------------------------
__global__ __launch_bounds__(256)
void pv_kernel() {
    const int qt = blockIdx.x, h = blockIdx.y;
    const int kvh = h >> 2;
    const int tid = threadIdx.x;
    const int tx = tid & 63;     // dim
    const int ty = tid >> 6;     // 0..3

    __shared__ float Ps[32][65];
    __shared__ float Vs[64][65];
    float acc[8] = {};

    for (int k0 = 0; k0 < S_LEN; k0 += 64) {
        for (int e = tid; e < 32 * 64; e += 256) {
            int r = e >> 6, c = e & 63;
            Ps[r][c] = g_sc[((size_t)h * S_LEN + qt * 32 + r) * S_LEN + k0 + c];
        }
        for (int e = tid; e < 64 * 64; e += 256) {
            int r = e >> 6, c = e & 63;
            Vs[r][c] = g_v[(size_t)(k0 + r) * KVDIM + kvh * HD + c];
        }
        __syncthreads();
#pragma unroll 16
        for (int kk = 0; kk < 64; kk++) {
            float vv = Vs[kk][tx];
#pragma unroll
            for (int m = 0; m < 8; m++)
                acc[m] = fmaf(Ps[ty + 4 * m][kk], vv, acc[m]);
        }
        __syncthreads();
    }
#pragma unroll
    for (int m = 0; m < 8; m++)
        g_ao[(size_t)(qt * 32 + ty + 4 * m) * DIM + h * HD + tx] = acc[m];
}

// ---------------------------------------------------------------------------
// Launch
// ---------------------------------------------------------------------------
extern "C" void kernel_launch(void* const* d_in, const int* in_sizes, int n_in,
                              void* d_out, int out_size) {
    const float* x  = (const float*)d_in[0];
    const float* wq = (const float*)d_in[1];
    const float* wk = (const float*)d_in[2];
    const float* wv = (const float*)d_in[3];
    const float* wo = (const float*)d_in[4];
    float* out = (float*)d_out;

    float* q  = nullptr; cudaGetSymbolAddress((void**)&q,  g_q);
    float* k  = nullptr; cudaGetSymbolAddress((void**)&k,  g_k);
    float* v  = nullptr; cudaGetSymbolAddress((void**)&v,  g_v);
    float* ao = nullptr; cudaGetSymbolAddress((void**)&ao, g_ao);

    // Projections: q = x@wq^T (2048x2048), k/v = x@w^T (2048x512)
    gemm_nt<<<dim3(DIM / 64,   S_LEN / 64), 256>>>(x, wq, q, S_LEN, DIM,   DIM);
    gemm_nt<<<dim3(KVDIM / 64, S_LEN / 64), 256>>>(x, wk, k, S_LEN, KVDIM, DIM);
    gemm_nt<<<dim3(KVDIM / 64, S_LEN / 64), 256>>>(x, wv, v, S_LEN, KVDIM, DIM);

    // RoPE
    rope_table_kernel<<<S_LEN, 32>>>();
    rope_apply_kernel<<<S_LEN, 256>>>();

    // Attention: scores -> softmax -> PV
    qk_kernel<<<dim3(S_LEN / 32, S_LEN / 32, NH), dim3(32, 32)>>>();
    softmax_kernel<<<dim3(S_LEN, NH), 256>>>();
    pv_kernel<<<dim3(S_LEN / 32, NH), 256>>>();

    // Output projection
    gemm_nt<<<dim3(DIM / 64, S_LEN / 64), 256>>>(ao, wo, out, S_LEN, DIM, DIM);
}

// round 3
// speedup vs baseline: 2.0361x; 2.0361x over previous
#include <cuda_runtime.h>
#include <cuda_bf16.h>
#include <math.h>

#define S_LEN 2048
#define DIM 2048
#define NH 32
#define NKV 8
#define HD 64
#define KVDIM (NKV * HD)   // 512

// ---------------------------------------------------------------------------
// Scratch (__device__ globals; no runtime allocation allowed)
// ---------------------------------------------------------------------------
__device__ float g_q[S_LEN * DIM];                       // 16 MB
__device__ float g_k[S_LEN * KVDIM];                     // 4 MB
__device__ float g_v[S_LEN * KVDIM];                     // 4 MB
__device__ float g_ao[S_LEN * DIM];                      // 16 MB
__device__ float g_sc[(size_t)NH * S_LEN * S_LEN];       // 537 MB scores/probs
__device__ float g_ct[S_LEN * 32];
__device__ float g_st[S_LEN * 32];

// ---------------------------------------------------------------------------
// SGEMM: C[M,N] = A[M,K] @ B[N,K]^T (row-major, K contiguous).
// BM=BN=128, BK=8, 256 threads, 8x8 per thread, float4 global loads.
// ---------------------------------------------------------------------------
__global__ __launch_bounds__(256)
void sgemm_nt(const float* __restrict__ A, const float* __restrict__ B,
              float* __restrict__ C, int M, int N, int K) {
    __shared__ float As[8][128];
    __shared__ float Bs[8][128];

    const int bx = blockIdx.x;   // N tile
    const int by = blockIdx.y;   // M tile
    const int tid = threadIdx.x;
    const int trow = tid >> 4;   // 0..15
    const int tcol = tid & 15;   // 0..15

    const float* Ab = A + (size_t)by * 128 * K;
    const float* Bb = B + (size_t)bx * 128 * K;

    const int lrow = tid >> 1;          // 0..127
    const int lk   = (tid & 1) * 4;     // 0 or 4

    float acc[8][8];
#pragma unroll
    for (int i = 0; i < 8; i++)
#pragma unroll
        for (int j = 0; j < 8; j++) acc[i][j] = 0.f;

    for (int k0 = 0; k0 < K; k0 += 8) {
        float4 a4 = *reinterpret_cast<const float4*>(Ab + (size_t)lrow * K + k0 + lk);
        float4 b4 = *reinterpret_cast<const float4*>(Bb + (size_t)lrow * K + k0 + lk);
        As[lk + 0][lrow] = a4.x; As[lk + 1][lrow] = a4.y;
        As[lk + 2][lrow] = a4.z; As[lk + 3][lrow] = a4.w;
        Bs[lk + 0][lrow] = b4.x; Bs[lk + 1][lrow] = b4.y;
        Bs[lk + 2][lrow] = b4.z; Bs[lk + 3][lrow] = b4.w;
        __syncthreads();

#pragma unroll
        for (int kk = 0; kk < 8; kk++) {
            float ar[8], br[8];
#pragma unroll
            for (int i = 0; i < 8; i++) ar[i] = As[kk][trow * 8 + i];
#pragma unroll
            for (int j = 0; j < 8; j++) br[j] = Bs[kk][tcol * 8 + j];
#pragma unroll
            for (int i = 0; i < 8; i++)
#pragma unroll
                for (int j = 0; j < 8; j++) acc[i][j] = fmaf(ar[i], br[j], acc[i][j]);
        }
        __syncthreads();
    }

#pragma unroll
    for (int i = 0; i < 8; i++) {
        float* crow = C + (size_t)(by * 128 + trow * 8 + i) * N + bx * 128 + tcol * 8;
        *reinterpret_cast<float4*>(crow)     = make_float4(acc[i][0], acc[i][1], acc[i][2], acc[i][3]);
        *reinterpret_cast<float4*>(crow + 4) = make_float4(acc[i][4], acc[i][5], acc[i][6], acc[i][7]);
    }
}

// ---------------------------------------------------------------------------
// RoPE cos/sin table (fp32 angle like reference, high-precision trig).
// ---------------------------------------------------------------------------
__global__ void rope_table_kernel() {
    int s = blockIdx.x;
    int i = threadIdx.x;   // 0..31
    float e = (float)i / 32.0f;
    float fr = 1.0f / powf(10000.0f, e);
    float angf = (float)s * fr;
    double ang = (double)angf;
    g_ct[s * 32 + i] = (float)cos(ang);
    g_st[s * 32 + i] = (float)sin(ang);
}

__global__ __launch_bounds__(256)
void rope_apply_kernel() {
    const int s = blockIdx.x;
    for (int item = threadIdx.x; item < (NH + NKV) * 32; item += 256) {
        float* base;
        int i;
        if (item < NH * 32) {
            int h = item >> 5; i = item & 31;
            base = g_q + (size_t)s * DIM + h * HD;
        } else {
            int it = item - NH * 32;
            int h = it >> 5; i = it & 31;
            base = g_k + (size_t)s * KVDIM + h * HD;
        }
        float c  = g_ct[s * 32 + i];
        float sn = g_st[s * 32 + i];
        float x1 = base[i], x2 = base[i + 32];
        base[i]      = x1 * c - x2 * sn;
        base[i + 32] = x2 * c + x1 * sn;
    }
}

// ---------------------------------------------------------------------------
// QK: raw scores (scaled) for lower-triangle 64x64 tiles only.
// grid (32 ktiles, 32 qtiles, 32 heads), 256 threads, 4x4 per thread.
// Upper-triangle tiles and intra-diagonal upper region are left unwritten;
// softmax only scans j<=q and pv zero-masks on load.
// ---------------------------------------------------------------------------
__global__ __launch_bounds__(256)
void qk_kernel() {
    const int kt = blockIdx.x, qt = blockIdx.y, h = blockIdx.z;
    if (kt > qt) return;
    const int kvh = h >> 2;
    const int tid = threadIdx.x;
    const int ty = tid >> 4;   // 0..15
    const int tx = tid & 15;   // 0..15

    __shared__ float Qs[64][65];   // [d][row]
    __shared__ float Ks[64][65];   // [d][col]

    // Load tiles transposed: Qs[d][r] = q[qt*64+r][h*64+d]
    for (int e = tid; e < 64 * 16; e += 256) {
        int r = e >> 4;
        int d4 = (e & 15) * 4;
        float4 f = *reinterpret_cast<const float4*>(
            g_q + (size_t)(qt * 64 + r) * DIM + h * HD + d4);
        Qs[d4 + 0][r] = f.x; Qs[d4 + 1][r] = f.y;
        Qs[d4 + 2][r] = f.z; Qs[d4 + 3][r] = f.w;
        float4 g = *reinterpret_cast<const float4*>(
            g_k + (size_t)(kt * 64 + r) * KVDIM + kvh * HD + d4);
        Ks[d4 + 0][r] = g.x; Ks[d4 + 1][r] = g.y;
        Ks[d4 + 2][r] = g.z; Ks[d4 + 3][r] = g.w;
    }
    __syncthreads();

    float acc[4][4] = {};
#pragma unroll 16
    for (int d = 0; d < 64; d++) {
        float a[4], b[4];
#pragma unroll
        for (int i = 0; i < 4; i++) a[i] = Qs[d][ty * 4 + i];
#pragma unroll
        for (int j = 0; j < 4; j++) b[j] = Ks[d][tx * 4 + j];
#pragma unroll
        for (int i = 0; i < 4; i++)
#pragma unroll
            for (int j = 0; j < 4; j++) acc[i][j] = fmaf(a[i], b[j], acc[i][j]);
    }

#pragma unroll
    for (int i = 0; i < 4; i++) {
        int qpos = qt * 64 + ty * 4 + i;
        float* row = g_sc + ((size_t)h * S_LEN + qpos) * S_LEN + kt * 64 + tx * 4;
        *reinterpret_cast<float4*>(row) = make_float4(
            acc[i][0] * 0.125f, acc[i][1] * 0.125f,
            acc[i][2] * 0.125f, acc[i][3] * 0.125f);
    }
}

// ---------------------------------------------------------------------------
// Exact softmax over valid prefix [0, q] of each row. grid (2048, 32).
// ---------------------------------------------------------------------------
__global__ __launch_bounds__(256)
void softmax_kernel() {
    const int q = blockIdx.x, h = blockIdx.y;
    const int L = q + 1;
    float* row = g_sc + ((size_t)h * S_LEN + q) * S_LEN;
    __shared__ float red[256];
    const int tid = threadIdx.x;

    float m = -INFINITY;
    for (int j = tid; j < L; j += 256) m = fmaxf(m, row[j]);
    red[tid] = m;
    __syncthreads();
    for (int s = 128; s > 0; s >>= 1) {
        if (tid < s) red[tid] = fmaxf(red[tid], red[tid + s]);
        __syncthreads();
    }
    m = red[0];
    __syncthreads();

    float e = 0.f;
    for (int j = tid; j < L; j += 256) {
        float p = expf(row[j] - m);
        row[j] = p;
        e += p;
    }
    red[tid] = e;
    __syncthreads();
    for (int s = 128; s > 0; s >>= 1) {
        if (tid < s) red[tid] += red[tid + s];
        __syncthreads();
    }
    const float inv = 1.0f / red[0];
    for (int j = tid; j < L; j += 256) row[j] *= inv;
}

// ---------------------------------------------------------------------------
// PV: ao[q, h*64+d] = sum_{k<=q} P[h][q][k] * v[k, (h>>2)*64+d]
// grid (32 qtiles, 32 heads), 256 threads, 4x4 per thread, causal k-bound.
// ---------------------------------------------------------------------------
__global__ __launch_bounds__(256)
void pv_kernel() {
    const int qt = blockIdx.x, h = blockIdx.y;
    const int kvh = h >> 2;
    const int tid = threadIdx.x;
    const int ty = tid >> 4;   // 0..15 (row group)
    const int tx = tid & 15;   // 0..15 (dim group)

    __shared__ float Ps[64][65];   // [row][k]
    __shared__ float Vs[64][64];   // [k][d]
    float acc[4][4] = {};

    const int kmax = (qt + 1) * 64;
    for (int k0 = 0; k0 < kmax; k0 += 64) {
        const bool diag = (k0 == qt * 64);
        for (int e = tid; e < 64 * 16; e += 256) {
            int r = e >> 4;
            int c4 = (e & 15) * 4;
            float4 f = *reinterpret_cast<const float4*>(
                g_sc + ((size_t)h * S_LEN + qt * 64 + r) * S_LEN + k0 + c4);
            if (diag) {   // zero-mask unwritten upper region of diagonal tile
                if (c4 + 0 > r) f.x = 0.f;
                if (c4 + 1 > r) f.y = 0.f;
                if (c4 + 2 > r) f.z = 0.f;
                if (c4 + 3 > r) f.w = 0.f;
            }
            Ps[r][c4 + 0] = f.x; Ps[r][c4 + 1] = f.y;
            Ps[r][c4 + 2] = f.z; Ps[r][c4 + 3] = f.w;

            float4 g = *reinterpret_cast<const float4*>(
                g_v + (size_t)(k0 + r) * KVDIM + kvh * HD + c4);
            Vs[r][c4 + 0] = g.x; Vs[r][c4 + 1] = g.y;
            Vs[r][c4 + 2] = g.z; Vs[r][c4 + 3] = g.w;
        }
        __syncthreads();

#pragma unroll 16
        for (int kk = 0; kk < 64; kk++) {
            float pr[4], vr[4];
#pragma unroll
            for (int i = 0; i < 4; i++) pr[i] = Ps[ty * 4 + i][kk];
#pragma unroll
            for (int j = 0; j < 4; j++) vr[j] = Vs[kk][tx * 4 + j];
#pragma unroll
            for (int i = 0; i < 4; i++)
#pragma unroll
                for (int j = 0; j < 4; j++) acc[i][j] = fmaf(pr[i], vr[j], acc[i][j]);
        }
        __syncthreads();
    }

#pragma unroll
    for (int i = 0; i < 4; i++) {
        float* orow = g_ao + (size_t)(qt * 64 + ty * 4 + i) * DIM + h * HD + tx * 4;
        *reinterpret_cast<float4*>(orow) =
            make_float4(acc[i][0], acc[i][1], acc[i][2], acc[i][3]);
    }
}

// ---------------------------------------------------------------------------
// Launch
// ---------------------------------------------------------------------------
extern "C" void kernel_launch(void* const* d_in, const int* in_sizes, int n_in,
                              void* d_out, int out_size) {
    const float* x  = (const float*)d_in[0];
    const float* wq = (const float*)d_in[1];
    const float* wk = (const float*)d_in[2];
    const float* wv = (const float*)d_in[3];
    const float* wo = (const float*)d_in[4];
    float* out = (float*)d_out;

    float* q  = nullptr; cudaGetSymbolAddress((void**)&q,  g_q);
    float* k  = nullptr; cudaGetSymbolAddress((void**)&k,  g_k);
    float* v  = nullptr; cudaGetSymbolAddress((void**)&v,  g_v);
    float* ao = nullptr; cudaGetSymbolAddress((void**)&ao, g_ao);

    // Projections
    sgemm_nt<<<dim3(DIM / 128,   S_LEN / 128), 256>>>(x, wq, q, S_LEN, DIM,   DIM);
    sgemm_nt<<<dim3(KVDIM / 128, S_LEN / 128), 256>>>(x, wk, k, S_LEN, KVDIM, DIM);
    sgemm_nt<<<dim3(KVDIM / 128, S_LEN / 128), 256>>>(x, wv, v, S_LEN, KVDIM, DIM);

    // RoPE
    rope_table_kernel<<<S_LEN, 32>>>();
    rope_apply_kernel<<<S_LEN, 256>>>();

    // Attention: lower-triangle scores -> prefix softmax -> bounded PV
    qk_kernel<<<dim3(S_LEN / 64, S_LEN / 64, NH), 256>>>();
    softmax_kernel<<<dim3(S_LEN, NH), 256>>>();
    pv_kernel<<<dim3(S_LEN / 64, NH), 256>>>();

    // Output projection
    sgemm_nt<<<dim3(DIM / 128, S_LEN / 128), 256>>>(ao, wo, out, S_LEN, DIM, DIM);
}

// round 5
// speedup vs baseline: 2.1465x; 1.0542x over previous
#include <cuda_runtime.h>
#include <cuda_bf16.h>
#include <math.h>

#define S_LEN 2048
#define DIM 2048
#define NH 32
#define NKV 8
#define HD 64
#define KVDIM (NKV * HD)   // 512

// ---------------------------------------------------------------------------
// Scratch (__device__ globals; no runtime allocation allowed)
// ---------------------------------------------------------------------------
__device__ float g_q[S_LEN * DIM];     // 16 MB
__device__ float g_k[S_LEN * KVDIM];   // 4 MB
__device__ float g_v[S_LEN * KVDIM];   // 4 MB
__device__ float g_ao[S_LEN * DIM];    // 16 MB
__device__ float g_ct[S_LEN * 32];
__device__ float g_st[S_LEN * 32];

// ---------------------------------------------------------------------------
// SGEMM: C[M,N] = A[M,K] @ B[N,K]^T (row-major, K contiguous).
// BM=BN=128, BK=8, 256 threads, 8x8 per thread, float4 global loads.
// ---------------------------------------------------------------------------
__global__ __launch_bounds__(256)
void sgemm_nt(const float* __restrict__ A, const float* __restrict__ B,
              float* __restrict__ C, int M, int N, int K) {
    __shared__ float As[8][128];
    __shared__ float Bs[8][128];

    const int bx = blockIdx.x;
    const int by = blockIdx.y;
    const int tid = threadIdx.x;
    const int trow = tid >> 4;
    const int tcol = tid & 15;

    const float* Ab = A + (size_t)by * 128 * K;
    const float* Bb = B + (size_t)bx * 128 * K;

    const int lrow = tid >> 1;
    const int lk   = (tid & 1) * 4;

    float acc[8][8];
#pragma unroll
    for (int i = 0; i < 8; i++)
#pragma unroll
        for (int j = 0; j < 8; j++) acc[i][j] = 0.f;

    for (int k0 = 0; k0 < K; k0 += 8) {
        float4 a4 = *reinterpret_cast<const float4*>(Ab + (size_t)lrow * K + k0 + lk);
        float4 b4 = *reinterpret_cast<const float4*>(Bb + (size_t)lrow * K + k0 + lk);
        As[lk + 0][lrow] = a4.x; As[lk + 1][lrow] = a4.y;
        As[lk + 2][lrow] = a4.z; As[lk + 3][lrow] = a4.w;
        Bs[lk + 0][lrow] = b4.x; Bs[lk + 1][lrow] = b4.y;
        Bs[lk + 2][lrow] = b4.z; Bs[lk + 3][lrow] = b4.w;
        __syncthreads();

#pragma unroll
        for (int kk = 0; kk < 8; kk++) {
            float ar[8], br[8];
#pragma unroll
            for (int i = 0; i < 8; i++) ar[i] = As[kk][trow * 8 + i];
#pragma unroll
            for (int j = 0; j < 8; j++) br[j] = Bs[kk][tcol * 8 + j];
#pragma unroll
            for (int i = 0; i < 8; i++)
#pragma unroll
                for (int j = 0; j < 8; j++) acc[i][j] = fmaf(ar[i], br[j], acc[i][j]);
        }
        __syncthreads();
    }

#pragma unroll
    for (int i = 0; i < 8; i++) {
        float* crow = C + (size_t)(by * 128 + trow * 8 + i) * N + bx * 128 + tcol * 8;
        *reinterpret_cast<float4*>(crow)     = make_float4(acc[i][0], acc[i][1], acc[i][2], acc[i][3]);
        *reinterpret_cast<float4*>(crow + 4) = make_float4(acc[i][4], acc[i][5], acc[i][6], acc[i][7]);
    }
}

// ---------------------------------------------------------------------------
// RoPE cos/sin table (fp32 angle like reference, high-precision trig).
// ---------------------------------------------------------------------------
__global__ void rope_table_kernel() {
    int s = blockIdx.x;
    int i = threadIdx.x;
    float e = (float)i / 32.0f;
    float fr = 1.0f / powf(10000.0f, e);
    float angf = (float)s * fr;
    double ang = (double)angf;
    g_ct[s * 32 + i] = (float)cos(ang);
    g_st[s * 32 + i] = (float)sin(ang);
}

__global__ __launch_bounds__(256)
void rope_apply_kernel() {
    const int s = blockIdx.x;
    for (int item = threadIdx.x; item < (NH + NKV) * 32; item += 256) {
        float* base;
        int i;
        if (item < NH * 32) {
            int h = item >> 5; i = item & 31;
            base = g_q + (size_t)s * DIM + h * HD;
        } else {
            int it = item - NH * 32;
            int h = it >> 5; i = it & 31;
            base = g_k + (size_t)s * KVDIM + h * HD;
        }
        float c  = g_ct[s * 32 + i];
        float sn = g_st[s * 32 + i];
        float x1 = base[i], x2 = base[i + 32];
        base[i]      = x1 * c - x2 * sn;
        base[i + 32] = x2 * c + x1 * sn;
    }
}

// ---------------------------------------------------------------------------
// Fused flash attention (causal, GQA).
// Grid (32 qtiles, 32 heads), 256 threads, 64x64 tiles, head_dim 64.
// Thread (tr,tc) in 16x16 grid owns rows 4tr..4tr+3 / cols 4tc..4tc+3.
// Per-row softmax stats m[4], l[4] in registers; row reductions via
// __shfl_xor over the 16-lane row group. Scale folded into Q at load.
// Ss uses stride 68 so float4 row stores stay 16B-aligned.
// ---------------------------------------------------------------------------
#define PAD 65
#define SPAD 68
#define LOG2E 1.4426950408889634f

__global__ __launch_bounds__(256)
void attn_kernel(const float* __restrict__ q, const float* __restrict__ k,
                 const float* __restrict__ v, float* __restrict__ out) {
    extern __shared__ float sm[];
    float* Qs = sm;                  // [d][row] 64x65
    float* Ks = Qs + 64 * PAD;       // [d][col] 64x65
    float* Vs = Ks + 64 * PAD;       // [k][d]   64x65
    float* Ss = Vs + 64 * PAD;       // [row][k] 64x68 (16B-aligned rows)

    const int qt = (int)gridDim.x - 1 - (int)blockIdx.x;   // heavy tiles first
    const int h  = blockIdx.y;
    const int kvh = h >> 2;
    const int tid = threadIdx.x;
    const int tr = tid >> 4, tc = tid & 15;

    // Q tile, transposed to [d][row], pre-scaled by 1/sqrt(64)
    for (int e = tid; e < 64 * 16; e += 256) {
        int r = e >> 4;
        int d4 = (e & 15) * 4;
        float4 f = *reinterpret_cast<const float4*>(
            q + (size_t)(qt * 64 + r) * DIM + h * HD + d4);
        Qs[(d4 + 0) * PAD + r] = f.x * 0.125f;
        Qs[(d4 + 1) * PAD + r] = f.y * 0.125f;
        Qs[(d4 + 2) * PAD + r] = f.z * 0.125f;
        Qs[(d4 + 3) * PAD + r] = f.w * 0.125f;
    }

    float m[4], l[4], o[4][4];
#pragma unroll
    for (int i = 0; i < 4; i++) {
        m[i] = -INFINITY; l[i] = 0.f;
#pragma unroll
        for (int j = 0; j < 4; j++) o[i][j] = 0.f;
    }

    for (int kt = 0; kt <= qt; kt++) {
        // K transposed to [d][col]; V as [k][d]
        for (int e = tid; e < 64 * 16; e += 256) {
            int r = e >> 4;
            int d4 = (e & 15) * 4;
            size_t rowoff = (size_t)(kt * 64 + r) * KVDIM + kvh * HD + d4;
            float4 f = *reinterpret_cast<const float4*>(k + rowoff);
            Ks[(d4 + 0) * PAD + r] = f.x;
            Ks[(d4 + 1) * PAD + r] = f.y;
            Ks[(d4 + 2) * PAD + r] = f.z;
            Ks[(d4 + 3) * PAD + r] = f.w;
            float4 g = *reinterpret_cast<const float4*>(v + rowoff);
            Vs[r * PAD + d4 + 0] = g.x;
            Vs[r * PAD + d4 + 1] = g.y;
            Vs[r * PAD + d4 + 2] = g.z;
            Vs[r * PAD + d4 + 3] = g.w;
        }
        __syncthreads();

        // S = Q @ K^T (pre-scaled)
        float acc[4][4] = {};
#pragma unroll 16
        for (int d = 0; d < 64; d++) {
            float a[4], b[4];
#pragma unroll
            for (int i = 0; i < 4; i++) a[i] = Qs[d * PAD + tr * 4 + i];
#pragma unroll
            for (int j = 0; j < 4; j++) b[j] = Ks[d * PAD + tc * 4 + j];
#pragma unroll
            for (int i = 0; i < 4; i++)
#pragma unroll
                for (int j = 0; j < 4; j++) acc[i][j] = fmaf(a[i], b[j], acc[i][j]);
        }

        // causal mask on diagonal tile
        if (kt == qt) {
#pragma unroll
            for (int i = 0; i < 4; i++) {
                int r = tr * 4 + i;
#pragma unroll
                for (int j = 0; j < 4; j++)
                    if (tc * 4 + j > r) acc[i][j] = -INFINITY;
            }
        }

        // Online softmax, per owned row; reductions across 16-lane row group
        float al[4];
#pragma unroll
        for (int i = 0; i < 4; i++) {
            float mx = fmaxf(fmaxf(acc[i][0], acc[i][1]),
                             fmaxf(acc[i][2], acc[i][3]));
            mx = fmaxf(mx, __shfl_xor_sync(0xffffffffu, mx, 1));
            mx = fmaxf(mx, __shfl_xor_sync(0xffffffffu, mx, 2));
            mx = fmaxf(mx, __shfl_xor_sync(0xffffffffu, mx, 4));
            mx = fmaxf(mx, __shfl_xor_sync(0xffffffffu, mx, 8));
            float newm = fmaxf(m[i], mx);
            al[i] = exp2f((m[i] - newm) * LOG2E);
            m[i] = newm;
            float sum = 0.f;
#pragma unroll
            for (int j = 0; j < 4; j++) {
                float p = exp2f((acc[i][j] - newm) * LOG2E);
                acc[i][j] = p;
                sum += p;
            }
            sum += __shfl_xor_sync(0xffffffffu, sum, 1);
            sum += __shfl_xor_sync(0xffffffffu, sum, 2);
            sum += __shfl_xor_sync(0xffffffffu, sum, 4);
            sum += __shfl_xor_sync(0xffffffffu, sum, 8);
            l[i] = l[i] * al[i] + sum;
            // stage p for the PV GEMM (SPAD keeps this 16B-aligned)
            *reinterpret_cast<float4*>(Ss + (tr * 4 + i) * SPAD + tc * 4) =
                make_float4(acc[i][0], acc[i][1], acc[i][2], acc[i][3]);
        }
        __syncthreads();

        // o = o*al + P @ V
#pragma unroll
        for (int i = 0; i < 4; i++)
#pragma unroll
            for (int j = 0; j < 4; j++) o[i][j] *= al[i];

#pragma unroll 16
        for (int kk = 0; kk < 64; kk++) {
            float pr[4], vr[4];
#pragma unroll
            for (int i = 0; i < 4; i++) pr[i] = Ss[(tr * 4 + i) * SPAD + kk];
#pragma unroll
            for (int j = 0; j < 4; j++) vr[j] = Vs[kk * PAD + tc * 4 + j];
#pragma unroll
            for (int i = 0; i < 4; i++)
#pragma unroll
                for (int j = 0; j < 4; j++) o[i][j] = fmaf(pr[i], vr[j], o[i][j]);
        }
        __syncthreads();
    }

#pragma unroll
    for (int i = 0; i < 4; i++) {
        float li = 1.0f / l[i];
        float* orow = out + (size_t)(qt * 64 + tr * 4 + i) * DIM + h * HD + tc * 4;
        *reinterpret_cast<float4*>(orow) = make_float4(
            o[i][0] * li, o[i][1] * li, o[i][2] * li, o[i][3] * li);
    }
}

// ---------------------------------------------------------------------------
// Launch
// ---------------------------------------------------------------------------
extern "C" void kernel_launch(void* const* d_in, const int* in_sizes, int n_in,
                              void* d_out, int out_size) {
    const float* x  = (const float*)d_in[0];
    const float* wq = (const float*)d_in[1];
    const float* wk = (const float*)d_in[2];
    const float* wv = (const float*)d_in[3];
    const float* wo = (const float*)d_in[4];
    float* out = (float*)d_out;

    float* q  = nullptr; cudaGetSymbolAddress((void**)&q,  g_q);
    float* k  = nullptr; cudaGetSymbolAddress((void**)&k,  g_k);
    float* v  = nullptr; cudaGetSymbolAddress((void**)&v,  g_v);
    float* ao = nullptr; cudaGetSymbolAddress((void**)&ao, g_ao);

    const int smem_attn = (3 * 64 * PAD + 64 * SPAD) * (int)sizeof(float); // 67328
    static bool configured = false;
    if (!configured) {
        cudaFuncSetAttribute(attn_kernel,
                             cudaFuncAttributeMaxDynamicSharedMemorySize, smem_attn);
        configured = true;
    }

    // Projections
    sgemm_nt<<<dim3(DIM / 128,   S_LEN / 128), 256>>>(x, wq, q, S_LEN, DIM,   DIM);
    sgemm_nt<<<dim3(KVDIM / 128, S_LEN / 128), 256>>>(x, wk, k, S_LEN, KVDIM, DIM);
    sgemm_nt<<<dim3(KVDIM / 128, S_LEN / 128), 256>>>(x, wv, v, S_LEN, KVDIM, DIM);

    // RoPE
    rope_table_kernel<<<S_LEN, 32>>>();
    rope_apply_kernel<<<S_LEN, 256>>>();

    // Fused causal GQA flash attention
    attn_kernel<<<dim3(S_LEN / 64, NH), 256, smem_attn>>>(q, k, v, ao);

    // Output projection
    sgemm_nt<<<dim3(DIM / 128, S_LEN / 128), 256>>>(ao, wo, out, S_LEN, DIM, DIM);
}

// round 7
// speedup vs baseline: 3.9707x; 1.8498x over previous
#include <cuda_runtime.h>
#include <cuda_bf16.h>
#include <math.h>
#include <stdint.h>

#define S_LEN 2048
#define DIM 2048
#define NH 32
#define NKV 8
#define HD 64
#define KVDIM (NKV * HD)   // 512

// ---------------------------------------------------------------------------
// Scratch
// ---------------------------------------------------------------------------
__device__ float g_q[S_LEN * DIM];
__device__ float g_k[S_LEN * KVDIM];
__device__ float g_v[S_LEN * KVDIM];
__device__ float g_ao[S_LEN * DIM];
__device__ float g_ct[S_LEN * 32];
__device__ float g_st[S_LEN * 32];

__device__ __forceinline__ uint32_t smem_u32(const void* p) {
    uint32_t a;
    asm("{ .reg .u64 t; cvta.to.shared.u64 t, %1; cvt.u32.u64 %0, t; }"
        : "=r"(a) : "l"(p));
    return a;
}

__device__ __forceinline__ void ldm_x4(uint32_t* r, uint32_t addr) {
    asm volatile("ldmatrix.sync.aligned.m8n8.x4.shared.b16 {%0,%1,%2,%3}, [%4];"
                 : "=r"(r[0]), "=r"(r[1]), "=r"(r[2]), "=r"(r[3]) : "r"(addr));
}

__device__ __forceinline__ void mma_bf16(float* d, const uint32_t* a,
                                         const uint32_t* b) {
    asm volatile(
        "mma.sync.aligned.m16n8k16.row.col.f32.bf16.bf16.f32 "
        "{%0,%1,%2,%3}, {%4,%5,%6,%7}, {%8,%9}, {%0,%1,%2,%3};"
        : "+f"(d[0]), "+f"(d[1]), "+f"(d[2]), "+f"(d[3])
        : "r"(a[0]), "r"(a[1]), "r"(a[2]), "r"(a[3]), "r"(b[0]), "r"(b[1]));
}

// ---------------------------------------------------------------------------
// Tensor-core GEMM via mma.sync bf16x3: C[M,N] = A[M,K] @ B[N,K]^T, fp32 io.
// CTA 128x128, BK=32, 256 threads (8 warps, 4x2), warp tile 32x64.
// ---------------------------------------------------------------------------
#define GPAD 40   // bf16 row stride (80 B, 16B-aligned, conflict-skewed)

__global__ __launch_bounds__(256)
void mma_gemm_nt(const float* __restrict__ A, const float* __restrict__ B,
                 float* __restrict__ C, int M, int N, int K) {
    __shared__ __align__(16) uint16_t sAh[128][GPAD];
    __shared__ __align__(16) uint16_t sAl[128][GPAD];
    __shared__ __align__(16) uint16_t sBh[128][GPAD];
    __shared__ __align__(16) uint16_t sBl[128][GPAD];

    const int tid  = threadIdx.x;
    const int wid  = tid >> 5;
    const int lane = tid & 31;
    const int wm = (wid & 3) * 32;   // warp row offset in tile
    const int wn = (wid >> 2) * 64;  // warp col offset in tile
    const int m0 = blockIdx.y * 128;
    const int n0 = blockIdx.x * 128;

    const uint32_t bAh = smem_u32(sAh), bAl = smem_u32(sAl);
    const uint32_t bBh = smem_u32(sBh), bBl = smem_u32(sBl);

    float acc[2][8][4];
#pragma unroll
    for (int i = 0; i < 2; i++)
#pragma unroll
        for (int j = 0; j < 8; j++)
#pragma unroll
            for (int e = 0; e < 4; e++) acc[i][j][e] = 0.f;

    // ldmatrix per-lane address offsets (elements)
    const int a_r = lane & 15;                         // row within 16
    const int a_c = (lane >> 4) << 3;                  // 0 or 8 (k)
    const int b_r = (lane & 7) + ((lane >> 4) << 3);   // n within 16
    const int b_c = ((lane >> 3) & 1) << 3;            // 0 or 8 (k)

    for (int k0 = 0; k0 < K; k0 += 32) {
        // stage 128x32 of A and B, split into bf16 hi/lo
        const float* Ag = A + (size_t)m0 * K + k0;
        const float* Bg = B + (size_t)n0 * K + k0;
#pragma unroll
        for (int it = 0; it < 4; it++) {
            int idx = tid + it * 256;        // 0..1023 over 128x8 float4
            int r = idx >> 3;
            int c4 = (idx & 7) * 4;
            float4 fa = *reinterpret_cast<const float4*>(Ag + (size_t)r * K + c4);
            float4 fb = *reinterpret_cast<const float4*>(Bg + (size_t)r * K + c4);

            __nv_bfloat162 ah0 = __float22bfloat162_rn(make_float2(fa.x, fa.y));
            __nv_bfloat162 ah1 = __float22bfloat162_rn(make_float2(fa.z, fa.w));
            __nv_bfloat162 al0 = __float22bfloat162_rn(make_float2(
                fa.x - __bfloat162float(ah0.x), fa.y - __bfloat162float(ah0.y)));
            __nv_bfloat162 al1 = __float22bfloat162_rn(make_float2(
                fa.z - __bfloat162float(ah1.x), fa.w - __bfloat162float(ah1.y)));
            __nv_bfloat162 bh0 = __float22bfloat162_rn(make_float2(fb.x, fb.y));
            __nv_bfloat162 bh1 = __float22bfloat162_rn(make_float2(fb.z, fb.w));
            __nv_bfloat162 bl0 = __float22bfloat162_rn(make_float2(
                fb.x - __bfloat162float(bh0.x), fb.y - __bfloat162float(bh0.y)));
            __nv_bfloat162 bl1 = __float22bfloat162_rn(make_float2(
                fb.z - __bfloat162float(bh1.x), fb.w - __bfloat162float(bh1.y)));

            *reinterpret_cast<uint32_t*>(&sAh[r][c4])     = *reinterpret_cast<uint32_t*>(&ah0);
            *reinterpret_cast<uint32_t*>(&sAh[r][c4 + 2]) = *reinterpret_cast<uint32_t*>(&ah1);
            *reinterpret_cast<uint32_t*>(&sAl[r][c4])     = *reinterpret_cast<uint32_t*>(&al0);
            *reinterpret_cast<uint32_t*>(&sAl[r][c4 + 2]) = *reinterpret_cast<uint32_t*>(&al1);
            *reinterpret_cast<uint32_t*>(&sBh[r][c4])     = *reinterpret_cast<uint32_t*>(&bh0);
            *reinterpret_cast<uint32_t*>(&sBh[r][c4 + 2]) = *reinterpret_cast<uint32_t*>(&bh1);
            *reinterpret_cast<uint32_t*>(&sBl[r][c4])     = *reinterpret_cast<uint32_t*>(&bl0);
            *reinterpret_cast<uint32_t*>(&sBl[r][c4 + 2]) = *reinterpret_cast<uint32_t*>(&bl1);
        }
        __syncthreads();

#pragma unroll
        for (int ks = 0; ks < 2; ks++) {
            const int kc = ks * 16;
            uint32_t ah[2][4], al[2][4];
#pragma unroll
            for (int mi = 0; mi < 2; mi++) {
                uint32_t off = (uint32_t)((wm + mi * 16 + a_r) * GPAD + kc + a_c) * 2;
                ldm_x4(ah[mi], bAh + off);
                ldm_x4(al[mi], bAl + off);
            }
            uint32_t bh[8][2], bl[8][2];
#pragma unroll
            for (int nj = 0; nj < 4; nj++) {
                uint32_t off = (uint32_t)((wn + nj * 16 + b_r) * GPAD + kc + b_c) * 2;
                uint32_t t[4];
                ldm_x4(t, bBh + off);
                bh[nj * 2][0] = t[0]; bh[nj * 2][1] = t[1];
                bh[nj * 2 + 1][0] = t[2]; bh[nj * 2 + 1][1] = t[3];
                ldm_x4(t, bBl + off);
                bl[nj * 2][0] = t[0]; bl[nj * 2][1] = t[1];
                bl[nj * 2 + 1][0] = t[2]; bl[nj * 2 + 1][1] = t[3];
            }
#pragma unroll
            for (int mi = 0; mi < 2; mi++)
#pragma unroll
                for (int ni = 0; ni < 8; ni++) {
                    mma_bf16(acc[mi][ni], ah[mi], bh[ni]);
                    mma_bf16(acc[mi][ni], ah[mi], bl[ni]);
                    mma_bf16(acc[mi][ni], al[mi], bh[ni]);
                }
        }
        __syncthreads();
    }

    // epilogue: lane g=lane>>2 rows, t=lane&3 col pairs
    const int g = lane >> 2, t = lane & 3;
#pragma unroll
    for (int mi = 0; mi < 2; mi++) {
        int r0 = m0 + wm + mi * 16 + g;
#pragma unroll
        for (int ni = 0; ni < 8; ni++) {
            int c = n0 + wn + ni * 8 + t * 2;
            *reinterpret_cast<float2*>(C + (size_t)r0 * N + c) =
                make_float2(acc[mi][ni][0], acc[mi][ni][1]);
            *reinterpret_cast<float2*>(C + (size_t)(r0 + 8) * N + c) =
                make_float2(acc[mi][ni][2], acc[mi][ni][3]);
        }
    }
}

// ---------------------------------------------------------------------------
// RoPE (verified path)
// ---------------------------------------------------------------------------
__global__ void rope_table_kernel() {
    int s = blockIdx.x;
    int i = threadIdx.x;
    float e = (float)i / 32.0f;
    float fr = 1.0f / powf(10000.0f, e);
    float angf = (float)s * fr;
    double ang = (double)angf;
    g_ct[s * 32 + i] = (float)cos(ang);
    g_st[s * 32 + i] = (float)sin(ang);
}

__global__ __launch_bounds__(256)
void rope_apply_kernel() {
    const int s = blockIdx.x;
    for (int item = threadIdx.x; item < (NH + NKV) * 32; item += 256) {
        float* base;
        int i;
        if (item < NH * 32) {
            int h = item >> 5; i = item & 31;
            base = g_q + (size_t)s * DIM + h * HD;
        } else {
            int it = item - NH * 32;
            int h = it >> 5; i = it & 31;
            base = g_k + (size_t)s * KVDIM + h * HD;
        }
        float c  = g_ct[s * 32 + i];
        float sn = g_st[s * 32 + i];
        float x1 = base[i], x2 = base[i + 32];
        base[i]      = x1 * c - x2 * sn;
        base[i + 32] = x2 * c + x1 * sn;
    }
}

// ---------------------------------------------------------------------------
// Fused flash attention (unchanged from R5 — passing)
// ---------------------------------------------------------------------------
#define PAD 65
#define SPAD 68
#define LOG2E 1.4426950408889634f

__global__ __launch_bounds__(256)
void attn_kernel(const float* __restrict__ q, const float* __restrict__ k,
                 const float* __restrict__ v, float* __restrict__ out) {
    extern __shared__ float sm[];
    float* Qs = sm;
    float* Ks = Qs + 64 * PAD;
    float* Vs = Ks + 64 * PAD;
    float* Ss = Vs + 64 * PAD;

    const int qt = (int)gridDim.x - 1 - (int)blockIdx.x;
    const int h  = blockIdx.y;
    const int kvh = h >> 2;
    const int tid = threadIdx.x;
    const int tr = tid >> 4, tc = tid & 15;

    for (int e = tid; e < 64 * 16; e += 256) {
        int r = e >> 4;
        int d4 = (e & 15) * 4;
        float4 f = *reinterpret_cast<const float4*>(
            q + (size_t)(qt * 64 + r) * DIM + h * HD + d4);
        Qs[(d4 + 0) * PAD + r] = f.x * 0.125f;
        Qs[(d4 + 1) * PAD + r] = f.y * 0.125f;
        Qs[(d4 + 2) * PAD + r] = f.z * 0.125f;
        Qs[(d4 + 3) * PAD + r] = f.w * 0.125f;
    }

    float m[4], l[4], o[4][4];
#pragma unroll
    for (int i = 0; i < 4; i++) {
        m[i] = -INFINITY; l[i] = 0.f;
#pragma unroll
        for (int j = 0; j < 4; j++) o[i][j] = 0.f;
    }

    for (int kt = 0; kt <= qt; kt++) {
        for (int e = tid; e < 64 * 16; e += 256) {
            int r = e >> 4;
            int d4 = (e & 15) * 4;
            size_t rowoff = (size_t)(kt * 64 + r) * KVDIM + kvh * HD + d4;
            float4 f = *reinterpret_cast<const float4*>(k + rowoff);
            Ks[(d4 + 0) * PAD + r] = f.x;
            Ks[(d4 + 1) * PAD + r] = f.y;
            Ks[(d4 + 2) * PAD + r] = f.z;
            Ks[(d4 + 3) * PAD + r] = f.w;
            float4 g = *reinterpret_cast<const float4*>(v + rowoff);
            Vs[r * PAD + d4 + 0] = g.x;
            Vs[r * PAD + d4 + 1] = g.y;
            Vs[r * PAD + d4 + 2] = g.z;
            Vs[r * PAD + d4 + 3] = g.w;
        }
        __syncthreads();

        float acc[4][4] = {};
#pragma unroll 16
        for (int d = 0; d < 64; d++) {
            float a[4], b[4];
#pragma unroll
            for (int i = 0; i < 4; i++) a[i] = Qs[d * PAD + tr * 4 + i];
#pragma unroll
            for (int j = 0; j < 4; j++) b[j] = Ks[d * PAD + tc * 4 + j];
#pragma unroll
            for (int i = 0; i < 4; i++)
#pragma unroll
                for (int j = 0; j < 4; j++) acc[i][j] = fmaf(a[i], b[j], acc[i][j]);
        }

        if (kt == qt) {
#pragma unroll
            for (int i = 0; i < 4; i++) {
                int r = tr * 4 + i;
#pragma unroll
                for (int j = 0; j < 4; j++)
                    if (tc * 4 + j > r) acc[i][j] = -INFINITY;
            }
        }

        float al[4];
#pragma unroll
        for (int i = 0; i < 4; i++) {
            float mx = fmaxf(fmaxf(acc[i][0], acc[i][1]),
                             fmaxf(acc[i][2], acc[i][3]));
            mx = fmaxf(mx, __shfl_xor_sync(0xffffffffu, mx, 1));
            mx = fmaxf(mx, __shfl_xor_sync(0xffffffffu, mx, 2));
            mx = fmaxf(mx, __shfl_xor_sync(0xffffffffu, mx, 4));
            mx = fmaxf(mx, __shfl_xor_sync(0xffffffffu, mx, 8));
            float newm = fmaxf(m[i], mx);
            al[i] = exp2f((m[i] - newm) * LOG2E);
            m[i] = newm;
            float sum = 0.f;
#pragma unroll
            for (int j = 0; j < 4; j++) {
                float p = exp2f((acc[i][j] - newm) * LOG2E);
                acc[i][j] = p;
                sum += p;
            }
            sum += __shfl_xor_sync(0xffffffffu, sum, 1);
            sum += __shfl_xor_sync(0xffffffffu, sum, 2);
            sum += __shfl_xor_sync(0xffffffffu, sum, 4);
            sum += __shfl_xor_sync(0xffffffffu, sum, 8);
            l[i] = l[i] * al[i] + sum;
            *reinterpret_cast<float4*>(Ss + (tr * 4 + i) * SPAD + tc * 4) =
                make_float4(acc[i][0], acc[i][1], acc[i][2], acc[i][3]);
        }
        __syncthreads();

#pragma unroll
        for (int i = 0; i < 4; i++)
#pragma unroll
            for (int j = 0; j < 4; j++) o[i][j] *= al[i];

#pragma unroll 16
        for (int kk = 0; kk < 64; kk++) {
            float pr[4], vr[4];
#pragma unroll
            for (int i = 0; i < 4; i++) pr[i] = Ss[(tr * 4 + i) * SPAD + kk];
#pragma unroll
            for (int j = 0; j < 4; j++) vr[j] = Vs[kk * PAD + tc * 4 + j];
#pragma unroll
            for (int i = 0; i < 4; i++)
#pragma unroll
                for (int j = 0; j < 4; j++) o[i][j] = fmaf(pr[i], vr[j], o[i][j]);
        }
        __syncthreads();
    }

#pragma unroll
    for (int i = 0; i < 4; i++) {
        float li = 1.0f / l[i];
        float* orow = out + (size_t)(qt * 64 + tr * 4 + i) * DIM + h * HD + tc * 4;
        *reinterpret_cast<float4*>(orow) = make_float4(
            o[i][0] * li, o[i][1] * li, o[i][2] * li, o[i][3] * li);
    }
}

// ---------------------------------------------------------------------------
// Launch
// ---------------------------------------------------------------------------
extern "C" void kernel_launch(void* const* d_in, const int* in_sizes, int n_in,
                              void* d_out, int out_size) {
    const float* x  = (const float*)d_in[0];
    const float* wq = (const float*)d_in[1];
    const float* wk = (const float*)d_in[2];
    const float* wv = (const float*)d_in[3];
    const float* wo = (const float*)d_in[4];
    float* out = (float*)d_out;

    float* q  = nullptr; cudaGetSymbolAddress((void**)&q,  g_q);
    float* k  = nullptr; cudaGetSymbolAddress((void**)&k,  g_k);
    float* v  = nullptr; cudaGetSymbolAddress((void**)&v,  g_v);
    float* ao = nullptr; cudaGetSymbolAddress((void**)&ao, g_ao);

    const int smem_attn = (3 * 64 * PAD + 64 * SPAD) * (int)sizeof(float); // 67328
    static bool configured = false;
    if (!configured) {
        cudaFuncSetAttribute(attn_kernel,
                             cudaFuncAttributeMaxDynamicSharedMemorySize, smem_attn);
        configured = true;
    }

    // Projections (mma.sync bf16x3 tensor cores)
    mma_gemm_nt<<<dim3(DIM / 128,   S_LEN / 128), 256>>>(x, wq, q, S_LEN, DIM,   DIM);
    mma_gemm_nt<<<dim3(KVDIM / 128, S_LEN / 128), 256>>>(x, wk, k, S_LEN, KVDIM, DIM);
    mma_gemm_nt<<<dim3(KVDIM / 128, S_LEN / 128), 256>>>(x, wv, v, S_LEN, KVDIM, DIM);

    // RoPE
    rope_table_kernel<<<S_LEN, 32>>>();
    rope_apply_kernel<<<S_LEN, 256>>>();

    // Fused causal GQA flash attention
    attn_kernel<<<dim3(S_LEN / 64, NH), 256, smem_attn>>>(q, k, v, ao);

    // Output projection
    mma_gemm_nt<<<dim3(DIM / 128, S_LEN / 128), 256>>>(ao, wo, out, S_LEN, DIM, DIM);
}

// round 8
// speedup vs baseline: 6.5633x; 1.6529x over previous
#include <cuda_runtime.h>
#include <cuda_bf16.h>
#include <math.h>
#include <stdint.h>

#define S_LEN 2048
#define DIM 2048
#define NH 32
#define NKV 8
#define HD 64
#define KVDIM (NKV * HD)   // 512

__device__ float g_q[S_LEN * DIM];
__device__ float g_k[S_LEN * KVDIM];
__device__ float g_v[S_LEN * KVDIM];
__device__ float g_ao[S_LEN * DIM];
__device__ float g_ct[S_LEN * 32];
__device__ float g_st[S_LEN * 32];

__device__ __forceinline__ uint32_t smem_u32(const void* p) {
    uint32_t a;
    asm("{ .reg .u64 t; cvta.to.shared.u64 t, %1; cvt.u32.u64 %0, t; }"
        : "=r"(a) : "l"(p));
    return a;
}

__device__ __forceinline__ void ldm_x4(uint32_t* r, uint32_t addr) {
    asm volatile("ldmatrix.sync.aligned.m8n8.x4.shared.b16 {%0,%1,%2,%3}, [%4];"
                 : "=r"(r[0]), "=r"(r[1]), "=r"(r[2]), "=r"(r[3]) : "r"(addr));
}
__device__ __forceinline__ void ldm_x4_t(uint32_t* r, uint32_t addr) {
    asm volatile("ldmatrix.sync.aligned.m8n8.x4.trans.shared.b16 {%0,%1,%2,%3}, [%4];"
                 : "=r"(r[0]), "=r"(r[1]), "=r"(r[2]), "=r"(r[3]) : "r"(addr));
}
__device__ __forceinline__ void mma_bf16(float* d, const uint32_t* a,
                                         const uint32_t* b) {
    asm volatile(
        "mma.sync.aligned.m16n8k16.row.col.f32.bf16.bf16.f32 "
        "{%0,%1,%2,%3}, {%4,%5,%6,%7}, {%8,%9}, {%0,%1,%2,%3};"
        : "+f"(d[0]), "+f"(d[1]), "+f"(d[2]), "+f"(d[3])
        : "r"(a[0]), "r"(a[1]), "r"(a[2]), "r"(a[3]), "r"(b[0]), "r"(b[1]));
}

__device__ __forceinline__ uint32_t pack_bf16(float x, float y) {
    __nv_bfloat162 t = __float22bfloat162_rn(make_float2(x, y));
    return *reinterpret_cast<uint32_t*>(&t);
}

// ---------------------------------------------------------------------------
// Tensor-core GEMM (unchanged from R7 — passing)
// ---------------------------------------------------------------------------
#define GPAD 40

__global__ __launch_bounds__(256)
void mma_gemm_nt(const float* __restrict__ A, const float* __restrict__ B,
                 float* __restrict__ C, int M, int N, int K) {
    __shared__ __align__(16) uint16_t sAh[128][GPAD];
    __shared__ __align__(16) uint16_t sAl[128][GPAD];
    __shared__ __align__(16) uint16_t sBh[128][GPAD];
    __shared__ __align__(16) uint16_t sBl[128][GPAD];

    const int tid  = threadIdx.x;
    const int wid  = tid >> 5;
    const int lane = tid & 31;
    const int wm = (wid & 3) * 32;
    const int wn = (wid >> 2) * 64;
    const int m0 = blockIdx.y * 128;
    const int n0 = blockIdx.x * 128;

    const uint32_t bAh = smem_u32(sAh), bAl = smem_u32(sAl);
    const uint32_t bBh = smem_u32(sBh), bBl = smem_u32(sBl);

    float acc[2][8][4];
#pragma unroll
    for (int i = 0; i < 2; i++)
#pragma unroll
        for (int j = 0; j < 8; j++)
#pragma unroll
            for (int e = 0; e < 4; e++) acc[i][j][e] = 0.f;

    const int a_r = lane & 15;
    const int a_c = (lane >> 4) << 3;
    const int b_r = (lane & 7) + ((lane >> 4) << 3);
    const int b_c = ((lane >> 3) & 1) << 3;

    for (int k0 = 0; k0 < K; k0 += 32) {
        const float* Ag = A + (size_t)m0 * K + k0;
        const float* Bg = B + (size_t)n0 * K + k0;
#pragma unroll
        for (int it = 0; it < 4; it++) {
            int idx = tid + it * 256;
            int r = idx >> 3;
            int c4 = (idx & 7) * 4;
            float4 fa = *reinterpret_cast<const float4*>(Ag + (size_t)r * K + c4);
            float4 fb = *reinterpret_cast<const float4*>(Bg + (size_t)r * K + c4);

            __nv_bfloat162 ah0 = __float22bfloat162_rn(make_float2(fa.x, fa.y));
            __nv_bfloat162 ah1 = __float22bfloat162_rn(make_float2(fa.z, fa.w));
            __nv_bfloat162 al0 = __float22bfloat162_rn(make_float2(
                fa.x - __bfloat162float(ah0.x), fa.y - __bfloat162float(ah0.y)));
            __nv_bfloat162 al1 = __float22bfloat162_rn(make_float2(
                fa.z - __bfloat162float(ah1.x), fa.w - __bfloat162float(ah1.y)));
            __nv_bfloat162 bh0 = __float22bfloat162_rn(make_float2(fb.x, fb.y));
            __nv_bfloat162 bh1 = __float22bfloat162_rn(make_float2(fb.z, fb.w));
            __nv_bfloat162 bl0 = __float22bfloat162_rn(make_float2(
                fb.x - __bfloat162float(bh0.x), fb.y - __bfloat162float(bh0.y)));
            __nv_bfloat162 bl1 = __float22bfloat162_rn(make_float2(
                fb.z - __bfloat162float(bh1.x), fb.w - __bfloat162float(bh1.y)));

            *reinterpret_cast<uint32_t*>(&sAh[r][c4])     = *reinterpret_cast<uint32_t*>(&ah0);
            *reinterpret_cast<uint32_t*>(&sAh[r][c4 + 2]) = *reinterpret_cast<uint32_t*>(&ah1);
            *reinterpret_cast<uint32_t*>(&sAl[r][c4])     = *reinterpret_cast<uint32_t*>(&al0);
            *reinterpret_cast<uint32_t*>(&sAl[r][c4 + 2]) = *reinterpret_cast<uint32_t*>(&al1);
            *reinterpret_cast<uint32_t*>(&sBh[r][c4])     = *reinterpret_cast<uint32_t*>(&bh0);
            *reinterpret_cast<uint32_t*>(&sBh[r][c4 + 2]) = *reinterpret_cast<uint32_t*>(&bh1);
            *reinterpret_cast<uint32_t*>(&sBl[r][c4])     = *reinterpret_cast<uint32_t*>(&bl0);
            *reinterpret_cast<uint32_t*>(&sBl[r][c4 + 2]) = *reinterpret_cast<uint32_t*>(&bl1);
        }
        __syncthreads();

#pragma unroll
        for (int ks = 0; ks < 2; ks++) {
            const int kc = ks * 16;
            uint32_t ah[2][4], al[2][4];
#pragma unroll
            for (int mi = 0; mi < 2; mi++) {
                uint32_t off = (uint32_t)((wm + mi * 16 + a_r) * GPAD + kc + a_c) * 2;
                ldm_x4(ah[mi], bAh + off);
                ldm_x4(al[mi], bAl + off);
            }
            uint32_t bh[8][2], bl[8][2];
#pragma unroll
            for (int nj = 0; nj < 4; nj++) {
                uint32_t off = (uint32_t)((wn + nj * 16 + b_r) * GPAD + kc + b_c) * 2;
                uint32_t t[4];
                ldm_x4(t, bBh + off);
                bh[nj * 2][0] = t[0]; bh[nj * 2][1] = t[1];
                bh[nj * 2 + 1][0] = t[2]; bh[nj * 2 + 1][1] = t[3];
                ldm_x4(t, bBl + off);
                bl[nj * 2][0] = t[0]; bl[nj * 2][1] = t[1];
                bl[nj * 2 + 1][0] = t[2]; bl[nj * 2 + 1][1] = t[3];
            }
#pragma unroll
            for (int mi = 0; mi < 2; mi++)
#pragma unroll
                for (int ni = 0; ni < 8; ni++) {
                    mma_bf16(acc[mi][ni], ah[mi], bh[ni]);
                    mma_bf16(acc[mi][ni], ah[mi], bl[ni]);
                    mma_bf16(acc[mi][ni], al[mi], bh[ni]);
                }
        }
        __syncthreads();
    }

    const int g = lane >> 2, t = lane & 3;
#pragma unroll
    for (int mi = 0; mi < 2; mi++) {
        int r0 = m0 + wm + mi * 16 + g;
#pragma unroll
        for (int ni = 0; ni < 8; ni++) {
            int c = n0 + wn + ni * 8 + t * 2;
            *reinterpret_cast<float2*>(C + (size_t)r0 * N + c) =
                make_float2(acc[mi][ni][0], acc[mi][ni][1]);
            *reinterpret_cast<float2*>(C + (size_t)(r0 + 8) * N + c) =
                make_float2(acc[mi][ni][2], acc[mi][ni][3]);
        }
    }
}

// ---------------------------------------------------------------------------
// RoPE (verified path)
// ---------------------------------------------------------------------------
__global__ void rope_table_kernel() {
    int s = blockIdx.x;
    int i = threadIdx.x;
    float e = (float)i / 32.0f;
    float fr = 1.0f / powf(10000.0f, e);
    float angf = (float)s * fr;
    double ang = (double)angf;
    g_ct[s * 32 + i] = (float)cos(ang);
    g_st[s * 32 + i] = (float)sin(ang);
}

__global__ __launch_bounds__(256)
void rope_apply_kernel() {
    const int s = blockIdx.x;
    for (int item = threadIdx.x; item < (NH + NKV) * 32; item += 256) {
        float* base;
        int i;
        if (item < NH * 32) {
            int h = item >> 5; i = item & 31;
            base = g_q + (size_t)s * DIM + h * HD;
        } else {
            int it = item - NH * 32;
            int h = it >> 5; i = it & 31;
            base = g_k + (size_t)s * KVDIM + h * HD;
        }
        float c  = g_ct[s * 32 + i];
        float sn = g_st[s * 32 + i];
        float x1 = base[i], x2 = base[i + 32];
        base[i]      = x1 * c - x2 * sn;
        base[i + 32] = x2 * c + x1 * sn;
    }
}

// ---------------------------------------------------------------------------
// Tensor-core flash attention (causal, GQA).
// Grid (32 qtiles, 32 heads), 128 threads (4 warps), 64x64 tiles.
// Warp w owns q-rows 16w..16w+15. QK: bf16x3; PV: PhiVhi+PhiVlo+PloVhi.
// P stays in registers (S C-fragment == PV A-fragment layout).
// ---------------------------------------------------------------------------
#define KPAD 72
#define LOG2E 1.4426950408889634f

__global__ __launch_bounds__(128)
void attn_tc_kernel(const float* __restrict__ q, const float* __restrict__ k,
                    const float* __restrict__ v, float* __restrict__ out) {
    __shared__ __align__(16) uint16_t sKh[64][KPAD];
    __shared__ __align__(16) uint16_t sKl[64][KPAD];
    __shared__ __align__(16) uint16_t sVh[64][KPAD];
    __shared__ __align__(16) uint16_t sVl[64][KPAD];

    const int qt = (int)gridDim.x - 1 - (int)blockIdx.x;
    const int h  = blockIdx.y;
    const int kvh = h >> 2;
    const int tid = threadIdx.x;
    const int wid = tid >> 5;
    const int lane = tid & 31;
    const int g = lane >> 2;        // C/A fragment row within 8
    const int t = lane & 3;         // fragment col pair

    const uint32_t bKh = smem_u32(sKh), bKl = smem_u32(sKl);
    const uint32_t bVh = smem_u32(sVh), bVl = smem_u32(sVl);

    // ---- stage Q (scaled) into sKh/sKl, pull fragments to registers ----
#pragma unroll
    for (int it = 0; it < 4; it++) {
        int idx = tid + it * 128;           // 512 float4 = 64x64 floats
        int r = idx >> 2;
        int c4 = (idx & 3) * 16;            // 4 float4 per row per thread? no:
        (void)c4;
    }
    // 64 rows x 16 float4 per row = 1024 float4; 128 threads x 8
#pragma unroll
    for (int it = 0; it < 8; it++) {
        int idx = tid + it * 128;
        int r = idx >> 4;
        int c4 = (idx & 15) * 4;
        float4 f = *reinterpret_cast<const float4*>(
            q + (size_t)(qt * 64 + r) * DIM + h * HD + c4);
        f.x *= 0.125f; f.y *= 0.125f; f.z *= 0.125f; f.w *= 0.125f;
        __nv_bfloat162 h0 = __float22bfloat162_rn(make_float2(f.x, f.y));
        __nv_bfloat162 h1 = __float22bfloat162_rn(make_float2(f.z, f.w));
        __nv_bfloat162 l0 = __float22bfloat162_rn(make_float2(
            f.x - __bfloat162float(h0.x), f.y - __bfloat162float(h0.y)));
        __nv_bfloat162 l1 = __float22bfloat162_rn(make_float2(
            f.z - __bfloat162float(h1.x), f.w - __bfloat162float(h1.y)));
        *reinterpret_cast<uint32_t*>(&sKh[r][c4])     = *reinterpret_cast<uint32_t*>(&h0);
        *reinterpret_cast<uint32_t*>(&sKh[r][c4 + 2]) = *reinterpret_cast<uint32_t*>(&h1);
        *reinterpret_cast<uint32_t*>(&sKl[r][c4])     = *reinterpret_cast<uint32_t*>(&l0);
        *reinterpret_cast<uint32_t*>(&sKl[r][c4 + 2]) = *reinterpret_cast<uint32_t*>(&l1);
    }
    __syncthreads();

    uint32_t qh[4][4], ql[4][4];
    {
        int row = wid * 16 + (lane & 15);
        int col = ((lane >> 4) & 1) * 8;
#pragma unroll
        for (int c = 0; c < 4; c++) {
            uint32_t off = (uint32_t)(row * KPAD + c * 16 + col) * 2;
            ldm_x4(qh[c], bKh + off);
            ldm_x4(ql[c], bKl + off);
        }
    }
    __syncthreads();

    float mr[2] = {-INFINITY, -INFINITY};
    float lr[2] = {0.f, 0.f};
    float D[8][4];
#pragma unroll
    for (int i = 0; i < 8; i++)
#pragma unroll
        for (int j = 0; j < 4; j++) D[i][j] = 0.f;

    // ldmatrix lane-address components (shared by all warps)
    const int kb_row = (lane & 7) + ((lane >> 4) << 3);   // K frags
    const int kb_col = ((lane >> 3) & 1) * 8;
    const int vb_row = (lane & 7) + (((lane >> 3) & 1) << 3);  // V trans frags
    const int vb_col = ((lane >> 4) & 1) * 8;

    for (int kt = 0; kt <= qt; kt++) {
        // ---- load K/V tile, bf16 split ----
#pragma unroll
        for (int it = 0; it < 8; it++) {
            int idx = tid + it * 128;
            int r = idx >> 4;
            int c4 = (idx & 15) * 4;
            size_t off = (size_t)(kt * 64 + r) * KVDIM + kvh * HD + c4;
            float4 f = *reinterpret_cast<const float4*>(k + off);
            __nv_bfloat162 h0 = __float22bfloat162_rn(make_float2(f.x, f.y));
            __nv_bfloat162 h1 = __float22bfloat162_rn(make_float2(f.z, f.w));
            __nv_bfloat162 l0 = __float22bfloat162_rn(make_float2(
                f.x - __bfloat162float(h0.x), f.y - __bfloat162float(h0.y)));
            __nv_bfloat162 l1 = __float22bfloat162_rn(make_float2(
                f.z - __bfloat162float(h1.x), f.w - __bfloat162float(h1.y)));
            *reinterpret_cast<uint32_t*>(&sKh[r][c4])     = *reinterpret_cast<uint32_t*>(&h0);
            *reinterpret_cast<uint32_t*>(&sKh[r][c4 + 2]) = *reinterpret_cast<uint32_t*>(&h1);
            *reinterpret_cast<uint32_t*>(&sKl[r][c4])     = *reinterpret_cast<uint32_t*>(&l0);
            *reinterpret_cast<uint32_t*>(&sKl[r][c4 + 2]) = *reinterpret_cast<uint32_t*>(&l1);

            float4 gv = *reinterpret_cast<const float4*>(v + off);
            __nv_bfloat162 vh0 = __float22bfloat162_rn(make_float2(gv.x, gv.y));
            __nv_bfloat162 vh1 = __float22bfloat162_rn(make_float2(gv.z, gv.w));
            __nv_bfloat162 vl0 = __float22bfloat162_rn(make_float2(
                gv.x - __bfloat162float(vh0.x), gv.y - __bfloat162float(vh0.y)));
            __nv_bfloat162 vl1 = __float22bfloat162_rn(make_float2(
                gv.z - __bfloat162float(vh1.x), gv.w - __bfloat162float(vh1.y)));
            *reinterpret_cast<uint32_t*>(&sVh[r][c4])     = *reinterpret_cast<uint32_t*>(&vh0);
            *reinterpret_cast<uint32_t*>(&sVh[r][c4 + 2]) = *reinterpret_cast<uint32_t*>(&vh1);
            *reinterpret_cast<uint32_t*>(&sVl[r][c4])     = *reinterpret_cast<uint32_t*>(&vl0);
            *reinterpret_cast<uint32_t*>(&sVl[r][c4 + 2]) = *reinterpret_cast<uint32_t*>(&vl1);
        }
        __syncthreads();

        // ---- S = Q K^T (bf16x3) ----
        float S[8][4];
#pragma unroll
        for (int i = 0; i < 8; i++)
#pragma unroll
            for (int j = 0; j < 4; j++) S[i][j] = 0.f;

#pragma unroll
        for (int c = 0; c < 4; c++) {
#pragma unroll
            for (int nbp = 0; nbp < 4; nbp++) {
                uint32_t kh[4], kl[4];
                uint32_t off = (uint32_t)((nbp * 16 + kb_row) * KPAD + c * 16 + kb_col) * 2;
                ldm_x4(kh, bKh + off);
                ldm_x4(kl, bKl + off);
                mma_bf16(S[2 * nbp],     qh[c], kh);
                mma_bf16(S[2 * nbp],     qh[c], kl);
                mma_bf16(S[2 * nbp],     ql[c], kh);
                mma_bf16(S[2 * nbp + 1], qh[c], kh + 2);
                mma_bf16(S[2 * nbp + 1], qh[c], kl + 2);
                mma_bf16(S[2 * nbp + 1], ql[c], kh + 2);
            }
        }

        // ---- causal mask (diagonal tile) ----
        if (kt == qt) {
            int r0 = wid * 16 + g;
#pragma unroll
            for (int nb = 0; nb < 8; nb++) {
                int c0 = nb * 8 + 2 * t;
                if (c0 > r0)     S[nb][0] = -INFINITY;
                if (c0 + 1 > r0) S[nb][1] = -INFINITY;
                if (c0 > r0 + 8)     S[nb][2] = -INFINITY;
                if (c0 + 1 > r0 + 8) S[nb][3] = -INFINITY;
            }
        }

        // ---- online softmax (rows g and g+8) ----
        float mx0 = -INFINITY, mx1 = -INFINITY;
#pragma unroll
        for (int nb = 0; nb < 8; nb++) {
            mx0 = fmaxf(mx0, fmaxf(S[nb][0], S[nb][1]));
            mx1 = fmaxf(mx1, fmaxf(S[nb][2], S[nb][3]));
        }
        mx0 = fmaxf(mx0, __shfl_xor_sync(0xffffffffu, mx0, 1));
        mx0 = fmaxf(mx0, __shfl_xor_sync(0xffffffffu, mx0, 2));
        mx1 = fmaxf(mx1, __shfl_xor_sync(0xffffffffu, mx1, 1));
        mx1 = fmaxf(mx1, __shfl_xor_sync(0xffffffffu, mx1, 2));
        float newm0 = fmaxf(mr[0], mx0);
        float newm1 = fmaxf(mr[1], mx1);
        float a0 = exp2f((mr[0] - newm0) * LOG2E);
        float a1 = exp2f((mr[1] - newm1) * LOG2E);
        mr[0] = newm0; mr[1] = newm1;

        float sum0 = 0.f, sum1 = 0.f;
#pragma unroll
        for (int nb = 0; nb < 8; nb++) {
            S[nb][0] = exp2f((S[nb][0] - newm0) * LOG2E);
            S[nb][1] = exp2f((S[nb][1] - newm0) * LOG2E);
            S[nb][2] = exp2f((S[nb][2] - newm1) * LOG2E);
            S[nb][3] = exp2f((S[nb][3] - newm1) * LOG2E);
            sum0 += S[nb][0] + S[nb][1];
            sum1 += S[nb][2] + S[nb][3];
        }
        sum0 += __shfl_xor_sync(0xffffffffu, sum0, 1);
        sum0 += __shfl_xor_sync(0xffffffffu, sum0, 2);
        sum1 += __shfl_xor_sync(0xffffffffu, sum1, 1);
        sum1 += __shfl_xor_sync(0xffffffffu, sum1, 2);
        lr[0] = lr[0] * a0 + sum0;
        lr[1] = lr[1] * a1 + sum1;

        // ---- pack P fragments (hi/lo) ----
        uint32_t ph[4][4], pl[4][4];
#pragma unroll
        for (int c = 0; c < 4; c++) {
            int nA = 2 * c, nB = 2 * c + 1;
            ph[c][0] = pack_bf16(S[nA][0], S[nA][1]);
            ph[c][1] = pack_bf16(S[nA][2], S[nA][3]);
            ph[c][2] = pack_bf16(S[nB][0], S[nB][1]);
            ph[c][3] = pack_bf16(S[nB][2], S[nB][3]);
            __nv_bfloat162* hp;
            hp = reinterpret_cast<__nv_bfloat162*>(&ph[c][0]);
            pl[c][0] = pack_bf16(S[nA][0] - __bfloat162float(hp->x),
                                 S[nA][1] - __bfloat162float(hp->y));
            hp = reinterpret_cast<__nv_bfloat162*>(&ph[c][1]);
            pl[c][1] = pack_bf16(S[nA][2] - __bfloat162float(hp->x),
                                 S[nA][3] - __bfloat162float(hp->y));
            hp = reinterpret_cast<__nv_bfloat162*>(&ph[c][2]);
            pl[c][2] = pack_bf16(S[nB][0] - __bfloat162float(hp->x),
                                 S[nB][1] - __bfloat162float(hp->y));
            hp = reinterpret_cast<__nv_bfloat162*>(&ph[c][3]);
            pl[c][3] = pack_bf16(S[nB][2] - __bfloat162float(hp->x),
                                 S[nB][3] - __bfloat162float(hp->y));
        }

        // ---- rescale D ----
#pragma unroll
        for (int db = 0; db < 8; db++) {
            D[db][0] *= a0; D[db][1] *= a0;
            D[db][2] *= a1; D[db][3] *= a1;
        }

        // ---- D += P V ----
#pragma unroll
        for (int c = 0; c < 4; c++) {
#pragma unroll
            for (int dbp = 0; dbp < 4; dbp++) {
                uint32_t vh[4], vl[4];
                uint32_t off = (uint32_t)((c * 16 + vb_row) * KPAD + dbp * 16 + vb_col) * 2;
                ldm_x4_t(vh, bVh + off);
                ldm_x4_t(vl, bVl + off);
                mma_bf16(D[2 * dbp],     ph[c], vh);
                mma_bf16(D[2 * dbp],     ph[c], vl);
                mma_bf16(D[2 * dbp],     pl[c], vh);
                mma_bf16(D[2 * dbp + 1], ph[c], vh + 2);
                mma_bf16(D[2 * dbp + 1], ph[c], vl + 2);
                mma_bf16(D[2 * dbp + 1], pl[c], vh + 2);
            }
        }
        __syncthreads();
    }

    // ---- epilogue ----
    float inv0 = 1.0f / lr[0];
    float inv1 = 1.0f / lr[1];
    int row0 = qt * 64 + wid * 16 + g;
#pragma unroll
    for (int db = 0; db < 8; db++) {
        int col = h * HD + db * 8 + 2 * t;
        *reinterpret_cast<float2*>(out + (size_t)row0 * DIM + col) =
            make_float2(D[db][0] * inv0, D[db][1] * inv0);
        *reinterpret_cast<float2*>(out + (size_t)(row0 + 8) * DIM + col) =
            make_float2(D[db][2] * inv1, D[db][3] * inv1);
    }
}

// ---------------------------------------------------------------------------
// Launch
// ---------------------------------------------------------------------------
extern "C" void kernel_launch(void* const* d_in, const int* in_sizes, int n_in,
                              void* d_out, int out_size) {
    const float* x  = (const float*)d_in[0];
    const float* wq = (const float*)d_in[1];
    const float* wk = (const float*)d_in[2];
    const float* wv = (const float*)d_in[3];
    const float* wo = (const float*)d_in[4];
    float* out = (float*)d_out;

    float* q  = nullptr; cudaGetSymbolAddress((void**)&q,  g_q);
    float* k  = nullptr; cudaGetSymbolAddress((void**)&k,  g_k);
    float* v  = nullptr; cudaGetSymbolAddress((void**)&v,  g_v);
    float* ao = nullptr; cudaGetSymbolAddress((void**)&ao, g_ao);

    // Projections (mma.sync bf16x3 tensor cores)
    mma_gemm_nt<<<dim3(DIM / 128,   S_LEN / 128), 256>>>(x, wq, q, S_LEN, DIM,   DIM);
    mma_gemm_nt<<<dim3(KVDIM / 128, S_LEN / 128), 256>>>(x, wk, k, S_LEN, KVDIM, DIM);
    mma_gemm_nt<<<dim3(KVDIM / 128, S_LEN / 128), 256>>>(x, wv, v, S_LEN, KVDIM, DIM);

    // RoPE
    rope_table_kernel<<<S_LEN, 32>>>();
    rope_apply_kernel<<<S_LEN, 256>>>();

    // Tensor-core causal GQA flash attention
    attn_tc_kernel<<<dim3(S_LEN / 64, NH), 128>>>(q, k, v, ao);

    // Output projection
    mma_gemm_nt<<<dim3(DIM / 128, S_LEN / 128), 256>>>(ao, wo, out, S_LEN, DIM, DIM);
}